// round 12
// baseline (speedup 1.0000x reference)
#include <cuda_runtime.h>
#include <cstdint>

// Problem constants
#define BATCH 4
#define SEQ   2048
#define DMODEL 1024
#define NHEADS 16
#define DHEAD  64
#define MROWS (BATCH*SEQ)   // 8192

// Scratch (allocation-free: __device__ globals)
__device__ float g_q [BATCH*NHEADS*SEQ*DHEAD];   // [B,H,L,dh] tf32-rounded (+q scaled)
__device__ float g_k [BATCH*NHEADS*SEQ*DHEAD];
__device__ float g_v [BATCH*NHEADS*SEQ*DHEAD];
__device__ float g_ao[MROWS*DMODEL];             // [B*L, D] tf32-rounded
__device__ float g_xr[MROWS*DMODEL];             // tf32-rounded x
__device__ float g_wr[4*DMODEL*DMODEL];          // tf32-rounded Wq,Wk,Wv,Wo

__device__ __forceinline__ float tf32f(float f) {
    uint32_t r;
    asm("cvt.rna.tf32.f32 %0, %1;" : "=r"(r) : "f"(f));
    return __uint_as_float(r);
}

#define LDSM4(r0,r1,r2,r3,addr) \
    asm volatile("ldmatrix.sync.aligned.m8n8.x4.shared.b16 {%0,%1,%2,%3}, [%4];" \
        : "=r"(r0),"=r"(r1),"=r"(r2),"=r"(r3) : "r"(addr))

#define MMA_TF32(c,a,b0,b1) \
    asm volatile("mma.sync.aligned.m16n8k8.row.col.f32.tf32.tf32.f32 " \
        "{%0,%1,%2,%3},{%4,%5,%6,%7},{%8,%9},{%0,%1,%2,%3};" \
        : "+f"(c[0]),"+f"(c[1]),"+f"(c[2]),"+f"(c[3]) \
        : "r"(a[0]),"r"(a[1]),"r"(a[2]),"r"(a[3]),"r"(b0),"r"(b1))

#define CP16(dst,src) \
    asm volatile("cp.async.cg.shared.global [%0], [%1], 16;" \
        :: "r"(dst), "l"(src) : "memory")
#define CPCOMMIT() asm volatile("cp.async.commit_group;" ::: "memory")
#define CPWAIT(n)  asm volatile("cp.async.wait_group %0;" :: "n"(n) : "memory")

// ---------------------------------------------------------------------------
// Pre-round passes: fp32 -> tf32-rounded fp32
// ---------------------------------------------------------------------------
__global__ void __launch_bounds__(256)
round_x_kernel(const float* __restrict__ src, float* __restrict__ dst, int n4)
{
    int i = blockIdx.x * 256 + threadIdx.x;
    if (i >= n4) return;
    float4 v = reinterpret_cast<const float4*>(src)[i];
    v.x = tf32f(v.x); v.y = tf32f(v.y); v.z = tf32f(v.z); v.w = tf32f(v.w);
    reinterpret_cast<float4*>(dst)[i] = v;
}

__global__ void __launch_bounds__(256)
round_w_kernel(const float* __restrict__ Wq, const float* __restrict__ Wk,
               const float* __restrict__ Wv, const float* __restrict__ Wo,
               float* __restrict__ dst)
{
    const int z = blockIdx.y;
    const float* src = (z == 0) ? Wq : (z == 1) ? Wk : (z == 2) ? Wv : Wo;
    int i = blockIdx.x * 256 + threadIdx.x;
    float4 v = reinterpret_cast<const float4*>(src)[i];
    v.x = tf32f(v.x); v.y = tf32f(v.y); v.z = tf32f(v.z); v.w = tf32f(v.w);
    reinterpret_cast<float4*>(dst + (size_t)z * DMODEL * DMODEL)[i] = v;
}

// ---------------------------------------------------------------------------
// tf32 GEMM: C = A @ W^T, operands pre-rounded. cp.async 3-stage pipeline.
// CTA 128x128x32, 128 threads (4 warps 2x2), warp tile 64x64.
// LDSM/MMA ratio 8/32 (was 6/16). 110592 B smem -> 2 CTAs/SM.
// ---------------------------------------------------------------------------
#define GSTF  9216
#define GWOFF 4608
#define GEMM_SMEM_BYTES (3*GSTF*4)   // 110592

__device__ __forceinline__ void gemm_load_stage(
    const float* __restrict__ A, const float* __restrict__ W,
    int m0, int n0, int k0, uint32_t sb, int tid)
{
    #pragma unroll
    for (int it = 0; it < 8; it++) {
        int idx = tid + it * 128;
        int row = idx >> 3, cg = idx & 7;
        CP16(sb + (uint32_t)((row*36 + cg*4) * 4),
             (const void*)&A[(size_t)(m0 + row) * DMODEL + k0 + cg*4]);
        CP16(sb + (uint32_t)((GWOFF + row*36 + cg*4) * 4),
             (const void*)&W[(size_t)(n0 + row) * DMODEL + k0 + cg*4]);
    }
}

template<int PERMUTE, int ROUND>
__device__ __forceinline__ void gemm_core(
    const float* __restrict__ A, const float* __restrict__ W,
    float* __restrict__ C, float scale)
{
    extern __shared__ float sm[];
    const int tid  = threadIdx.x;
    const int lane = tid & 31;
    const int wid  = tid >> 5;         // 0..3
    const int m0 = blockIdx.y * 128;
    const int n0 = blockIdx.x * 128;
    const int wm = (wid & 1) * 64;
    const int wn = (wid >> 1) * 64;

    float c[4][8][4];
    #pragma unroll
    for (int i = 0; i < 4; i++)
        #pragma unroll
        for (int j = 0; j < 8; j++)
            #pragma unroll
            for (int r = 0; r < 4; r++) c[i][j][r] = 0.0f;

    uint32_t sb = (uint32_t)__cvta_generic_to_shared(sm);
    uint32_t a_addr[4], b_addr[4];
    #pragma unroll
    for (int i = 0; i < 4; i++)
        a_addr[i] = sb + ((wm + i*16 + (lane & 15)) * 36 + (lane >> 4) * 4) * 4;
    #pragma unroll
    for (int p = 0; p < 4; p++)
        b_addr[p] = sb + (GWOFF +
            (wn + p*16 + ((lane >> 4) & 1) * 8 + (lane & 7)) * 36
            + ((lane >> 3) & 1) * 4) * 4;

    const int NK = DMODEL / 32;   // 32 k-slabs

    gemm_load_stage(A, W, m0, n0, 0,  sb,            tid); CPCOMMIT();
    gemm_load_stage(A, W, m0, n0, 32, sb + GSTF*4,   tid); CPCOMMIT();
    gemm_load_stage(A, W, m0, n0, 64, sb + 2*GSTF*4, tid); CPCOMMIT();

    #pragma unroll 1
    for (int i = 0; i < NK; i++) {
        CPWAIT(2);          // stage i complete
        __syncthreads();

        const uint32_t soff = (uint32_t)(i % 3) * (GSTF*4);
        #pragma unroll
        for (int s = 0; s < 4; s++) {
            uint32_t a[4][4], bb[4][4];
            #pragma unroll
            for (int ii = 0; ii < 4; ii++)
                LDSM4(a[ii][0], a[ii][1], a[ii][2], a[ii][3],
                      a_addr[ii] + soff + s*32);
            #pragma unroll
            for (int p = 0; p < 4; p++)
                LDSM4(bb[p][0], bb[p][1], bb[p][2], bb[p][3],
                      b_addr[p] + soff + s*32);
            #pragma unroll
            for (int ii = 0; ii < 4; ii++)
                #pragma unroll
                for (int p = 0; p < 4; p++) {
                    MMA_TF32(c[ii][2*p],   a[ii], bb[p][0], bb[p][1]);
                    MMA_TF32(c[ii][2*p+1], a[ii], bb[p][2], bb[p][3]);
                }
        }
        __syncthreads();    // all reads of stage i%3 done
        if (i + 3 < NK)
            gemm_load_stage(A, W, m0, n0, (i+3)*32, sb + soff, tid);
        CPCOMMIT();
    }

    // Epilogue
    const int g  = lane >> 2;
    const int tq = lane & 3;
    #pragma unroll
    for (int i = 0; i < 4; i++) {
        #pragma unroll
        for (int j = 0; j < 8; j++) {
            int col = n0 + wn + j*8 + tq*2;
            #pragma unroll
            for (int t = 0; t < 2; t++) {
                int row = m0 + wm + i*16 + g + t*8;
                float v0 = c[i][j][2*t], v1 = c[i][j][2*t+1];
                if (ROUND) { v0 = tf32f(v0 * scale); v1 = tf32f(v1 * scale); }
                float2 v = make_float2(v0, v1);
                if (PERMUTE) {
                    int b = row >> 11, l = row & (SEQ - 1);
                    int h = col >> 6, d = col & 63;
                    *reinterpret_cast<float2*>(
                        &C[(((size_t)(b*NHEADS + h)) * SEQ + l) * DHEAD + d]) = v;
                } else {
                    *reinterpret_cast<float2*>(&C[(size_t)row * DMODEL + col]) = v;
                }
            }
        }
    }
}

__global__ void __launch_bounds__(128, 2)
gemm_qkv_kernel(const float* __restrict__ xr, const float* __restrict__ wr,
                float* __restrict__ q, float* __restrict__ k,
                float* __restrict__ v)
{
    const int z = blockIdx.z;
    const float* W = wr + (size_t)z * DMODEL * DMODEL;
    float* C = (z == 0) ? q : (z == 1) ? k : v;
    float scale = (z == 0) ? 0.125f : 1.0f;
    gemm_core<1, 1>(xr, W, C, scale);
}

__global__ void __launch_bounds__(128, 2)
gemm_o_kernel(const float* __restrict__ ao, const float* __restrict__ wr,
              float* __restrict__ out)
{
    gemm_core<0, 0>(ao, wr + (size_t)3 * DMODEL * DMODEL, out, 1.0f);
}

// ---------------------------------------------------------------------------
// Flash attention, tf32 mma (unchanged from round 11 — current best).
// CTA = 128 q x (b,h), 128 threads, 4 warps, warp tile m32 x n64, BK=64.
// Swizzled smem (256B rows, chunk^=(row&7)); K double-buffered.
//   Qs[128*64] | Ps[128*64] | Ks[2][64*64] | Vt[64*64] = 114688 B, 2 CTAs/SM.
// ---------------------------------------------------------------------------
#define AQS 0
#define APS 8192
#define AKS 16384
#define AKSTG 4096
#define AVT 24576
#define ATTN_SMEM_BYTES (28672*4)   // 114688

__global__ void __launch_bounds__(128, 2)
attn_tf32(const float* __restrict__ gq, const float* __restrict__ gk,
          const float* __restrict__ gv, float* __restrict__ ao)
{
    extern __shared__ float sm[];
    float* Ps  = sm + APS;
    float* Vts = sm + AVT;

    const int tid  = threadIdx.x;
    const int lane = tid & 31;
    const int wid  = tid >> 5;                    // 0..3, owns 32 q rows
    const int bh = blockIdx.y;
    const int q0 = ((int)gridDim.x - 1 - (int)blockIdx.x) * 128;  // heavy first

    uint32_t smb  = (uint32_t)__cvta_generic_to_shared(sm);
    uint32_t qs_b = smb + AQS*4;
    uint32_t ps_b = smb + APS*4;
    uint32_t ks_b = smb + AKS*4;
    uint32_t vt_b = smb + AVT*4;

    const float4* qbase = reinterpret_cast<const float4*>(
        gq + ((size_t)bh * SEQ + q0) * DHEAD);
    const float* kko = gk + (size_t)bh * SEQ * DHEAD;
    const float4* vvo = reinterpret_cast<const float4*>(
        gv + (size_t)bh * SEQ * DHEAD);

    // Prologue: cp.async Q + K0 (swizzled dst), register transpose-gather V0
    #pragma unroll
    for (int it = 0; it < 16; it++) {
        int idx = tid + it * 128;
        int row = idx >> 4, cg = idx & 15;
        CP16(qs_b + (uint32_t)((row << 8) + (((cg ^ (row & 7))) << 4)),
             (const void*)(qbase + idx));
    }
    #pragma unroll
    for (int it = 0; it < 8; it++) {
        int idx = tid + it * 128;
        int row = idx >> 4, cg = idx & 15;
        CP16(ks_b + (uint32_t)((row << 8) + ((cg ^ (row & 7)) << 4)),
             (const void*)(kko + (size_t)row * DHEAD + cg*4));
    }
    CPCOMMIT();
    float4 ra[8];
    #pragma unroll
    for (int it = 0; it < 8; it++) {
        int idx = tid + it * 128;
        ra[it] = vvo[(idx & 63) * 16 + (idx >> 6)];   // V[r][cg*4..+3]
    }

    // LDSM row bases (swizzle chunk added per s)
    const int rx   = lane & 7;
    const int c0qp = lane >> 4;
    const int c0kv = (lane >> 3) & 1;
    uint32_t qrow[2], prow_b[2];
    #pragma unroll
    for (int mi = 0; mi < 2; mi++) {
        uint32_t r = (uint32_t)(wid*32 + mi*16 + (lane & 15));
        qrow[mi]   = qs_b + (r << 8);
        prow_b[mi] = ps_b + (r << 8);
    }
    uint32_t kvrow[4];
    #pragma unroll
    for (int p = 0; p < 4; p++)
        kvrow[p] = (uint32_t)(p*16 + ((lane >> 4) & 1) * 8 + (lane & 7)) << 8;

    float m_i[2][2] = {{-1e30f, -1e30f}, {-1e30f, -1e30f}};
    float l_i[2][2] = {{0.0f, 0.0f}, {0.0f, 0.0f}};
    float o[2][8][4];
    #pragma unroll
    for (int mi = 0; mi < 2; mi++)
        #pragma unroll
        for (int j = 0; j < 8; j++)
            #pragma unroll
            for (int r = 0; r < 4; r++) o[mi][j][r] = 0.0f;

    const int g  = lane >> 2;
    const int tq = lane & 3;

    const int nkb = (q0 + 128) / 64;
    #pragma unroll 1
    for (int kb = 0; kb < nkb; kb++) {
        const int cur = kb & 1;
        const uint32_t kcur = ks_b + (uint32_t)cur * (AKSTG*4);

        if (kb > 0) __syncthreads();

        // Store prefetched V[kb] transposed into Vt (swizzled)
        #pragma unroll
        for (int it = 0; it < 8; it++) {
            int idx = tid + it * 128;
            int r = idx & 63, cg = idx >> 6;
            #pragma unroll
            for (int j = 0; j < 4; j++) {
                int rowd = cg*4 + j;
                float val = (j == 0) ? ra[it].x : (j == 1) ? ra[it].y
                          : (j == 2) ? ra[it].z : ra[it].w;
                Vts[(rowd << 6) + (((r >> 2) ^ (rowd & 7)) << 2) + (r & 3)] = val;
            }
        }
        CPWAIT(0);
        __syncthreads();

        // Issue K[kb+1] into other stage
        if (kb + 1 < nkb) {
            const float* knxt = kko + (size_t)(kb+1) * 64 * DHEAD;
            uint32_t kdst = ks_b + (uint32_t)(cur ^ 1) * (AKSTG*4);
            #pragma unroll
            for (int it = 0; it < 8; it++) {
                int idx = tid + it * 128;
                int row = idx >> 4, cg = idx & 15;
                CP16(kdst + (uint32_t)((row << 8) + ((cg ^ (row & 7)) << 4)),
                     (const void*)(knxt + (size_t)row * DHEAD + cg*4));
            }
            CPCOMMIT();
        }

        // S = Q @ K^T : warp m32 x n64 x k64
        float sf[2][8][4];
        #pragma unroll
        for (int mi = 0; mi < 2; mi++)
            #pragma unroll
            for (int j = 0; j < 8; j++)
                #pragma unroll
                for (int r = 0; r < 4; r++) sf[mi][j][r] = 0.0f;

        #pragma unroll
        for (int s = 0; s < 8; s++) {
            const uint32_t cq = (uint32_t)(((c0qp + 2*s) ^ rx) << 4);
            const uint32_t ck = (uint32_t)(((c0kv + 2*s) ^ rx) << 4);
            uint32_t a[2][4], bb[4][4];
            #pragma unroll
            for (int mi = 0; mi < 2; mi++)
                LDSM4(a[mi][0], a[mi][1], a[mi][2], a[mi][3], qrow[mi] + cq);
            #pragma unroll
            for (int p = 0; p < 4; p++)
                LDSM4(bb[p][0], bb[p][1], bb[p][2], bb[p][3],
                      kcur + kvrow[p] + ck);
            #pragma unroll
            for (int mi = 0; mi < 2; mi++)
                #pragma unroll
                for (int p = 0; p < 4; p++) {
                    MMA_TF32(sf[mi][2*p],   a[mi], bb[p][0], bb[p][1]);
                    MMA_TF32(sf[mi][2*p+1], a[mi], bb[p][2], bb[p][3]);
                }
        }

        // Causal mask (near diagonal only)
        const int k0 = kb * 64;
        if (k0 + 63 > q0 + wid*32) {
            #pragma unroll
            for (int mi = 0; mi < 2; mi++)
                #pragma unroll
                for (int t = 0; t < 2; t++) {
                    int qg = q0 + wid*32 + mi*16 + g + t*8;
                    #pragma unroll
                    for (int j = 0; j < 8; j++) {
                        int kg = k0 + j*8 + tq*2;
                        if (kg   > qg) sf[mi][j][2*t]   = -1e30f;
                        if (kg+1 > qg) sf[mi][j][2*t+1] = -1e30f;
                    }
                }
        }

        // Online softmax; write P (tf32) to warp-private Ps rows (swizzled)
        #pragma unroll
        for (int mi = 0; mi < 2; mi++)
            #pragma unroll
            for (int t = 0; t < 2; t++) {
                float mx = -1e30f;
                #pragma unroll
                for (int j = 0; j < 8; j++)
                    mx = fmaxf(mx, fmaxf(sf[mi][j][2*t], sf[mi][j][2*t+1]));
                mx = fmaxf(mx, __shfl_xor_sync(0xffffffffu, mx, 1));
                mx = fmaxf(mx, __shfl_xor_sync(0xffffffffu, mx, 2));
                float newm = fmaxf(m_i[mi][t], mx);
                float corr = __expf(m_i[mi][t] - newm);
                float rs = 0.0f;
                int prow = wid*32 + mi*16 + g + t*8;
                int pbase = (prow << 6) + ((tq & 1) << 1);
                #pragma unroll
                for (int j = 0; j < 8; j++) {
                    float p0 = __expf(sf[mi][j][2*t]   - newm);
                    float p1 = __expf(sf[mi][j][2*t+1] - newm);
                    rs += p0 + p1;
                    int ch = ((tq >> 1) + 2*j) ^ g;
                    *reinterpret_cast<float2*>(&Ps[pbase + (ch << 2)]) =
                        make_float2(tf32f(p0), tf32f(p1));
                }
                rs += __shfl_xor_sync(0xffffffffu, rs, 1);
                rs += __shfl_xor_sync(0xffffffffu, rs, 2);
                l_i[mi][t] = l_i[mi][t] * corr + rs;
                m_i[mi][t] = newm;
                #pragma unroll
                for (int j = 0; j < 8; j++) {
                    o[mi][j][2*t]   *= corr;
                    o[mi][j][2*t+1] *= corr;
                }
            }
        __syncwarp();

        // Prefetch V[kb+1]
        if (kb + 1 < nkb) {
            const float4* vnxt = vvo + (size_t)(kb+1) * 64 * DHEAD / 4;
            #pragma unroll
            for (int it = 0; it < 8; it++) {
                int idx = tid + it * 128;
                ra[it] = vnxt[(idx & 63) * 16 + (idx >> 6)];
            }
        }

        // O += P @ V : warp m32(q) x n64(d) x k64(keys)
        #pragma unroll
        for (int s = 0; s < 8; s++) {
            const uint32_t cq = (uint32_t)(((c0qp + 2*s) ^ rx) << 4);
            const uint32_t ck = (uint32_t)(((c0kv + 2*s) ^ rx) << 4);
            uint32_t a[2][4], bb[4][4];
            #pragma unroll
            for (int mi = 0; mi < 2; mi++)
                LDSM4(a[mi][0], a[mi][1], a[mi][2], a[mi][3], prow_b[mi] + cq);
            #pragma unroll
            for (int p = 0; p < 4; p++)
                LDSM4(bb[p][0], bb[p][1], bb[p][2], bb[p][3],
                      vt_b + kvrow[p] + ck);
            #pragma unroll
            for (int mi = 0; mi < 2; mi++)
                #pragma unroll
                for (int p = 0; p < 4; p++) {
                    MMA_TF32(o[mi][2*p],   a[mi], bb[p][0], bb[p][1]);
                    MMA_TF32(o[mi][2*p+1], a[mi], bb[p][2], bb[p][3]);
                }
        }
    }

    // Normalize and write tf32-rounded to [B*L, D] (col = h*64 + d)
    const int b = bh >> 4;
    const int h = bh & 15;
    #pragma unroll
    for (int mi = 0; mi < 2; mi++)
        #pragma unroll
        for (int t = 0; t < 2; t++) {
            float inv = 1.0f / l_i[mi][t];
            int row = q0 + wid*32 + mi*16 + g + t*8;
            float* dst = ao + ((size_t)(b * SEQ + row)) * DMODEL + h * DHEAD + tq*2;
            #pragma unroll
            for (int j = 0; j < 8; j++)
                *reinterpret_cast<float2*>(dst + j*8) =
                    make_float2(tf32f(o[mi][j][2*t] * inv),
                                tf32f(o[mi][j][2*t+1] * inv));
        }
}

// ---------------------------------------------------------------------------
extern "C" void kernel_launch(void* const* d_in, const int* in_sizes, int n_in,
                              void* d_out, int out_size)
{
    const float* x  = (const float*)d_in[0];
    const float* Wq = (const float*)d_in[1];
    const float* Wk = (const float*)d_in[2];
    const float* Wv = (const float*)d_in[3];
    const float* Wo = (const float*)d_in[4];
    float* out = (float*)d_out;

    float *qp, *kp, *vp, *aop, *xrp, *wrp;
    cudaGetSymbolAddress((void**)&qp,  g_q);
    cudaGetSymbolAddress((void**)&kp,  g_k);
    cudaGetSymbolAddress((void**)&vp,  g_v);
    cudaGetSymbolAddress((void**)&aop, g_ao);
    cudaGetSymbolAddress((void**)&xrp, g_xr);
    cudaGetSymbolAddress((void**)&wrp, g_wr);

    cudaFuncSetAttribute(gemm_qkv_kernel,
        cudaFuncAttributeMaxDynamicSharedMemorySize, GEMM_SMEM_BYTES);
    cudaFuncSetAttribute(gemm_o_kernel,
        cudaFuncAttributeMaxDynamicSharedMemorySize, GEMM_SMEM_BYTES);
    cudaFuncSetAttribute(attn_tf32,
        cudaFuncAttributeMaxDynamicSharedMemorySize, ATTN_SMEM_BYTES);

    const int n4x = MROWS * DMODEL / 4;
    const int n4w = DMODEL * DMODEL / 4;
    round_x_kernel<<<n4x/256, 256>>>(x, xrp, n4x);
    dim3 wgrid(n4w/256, 4);
    round_w_kernel<<<wgrid, 256>>>(Wq, Wk, Wv, Wo, wrp);

    dim3 qkv_grid(DMODEL/128, MROWS/128, 3);   // (8, 64, 3)
    gemm_qkv_kernel<<<qkv_grid, 128, GEMM_SMEM_BYTES>>>(xrp, wrp, qp, kp, vp);

    dim3 attn_grid(SEQ/128, BATCH*NHEADS);     // (16, 64)
    attn_tf32<<<attn_grid, 128, ATTN_SMEM_BYTES>>>(qp, kp, vp, aop);

    dim3 o_grid(DMODEL/128, MROWS/128);        // (8, 64)
    gemm_o_kernel<<<o_grid, 128, GEMM_SMEM_BYTES>>>(aop, wrp, out);
}

// round 13
// speedup vs baseline: 1.0607x; 1.0607x over previous
#include <cuda_runtime.h>
#include <cstdint>

// Problem constants
#define BATCH 4
#define SEQ   2048
#define DMODEL 1024
#define NHEADS 16
#define DHEAD  64
#define MROWS (BATCH*SEQ)   // 8192

// Scratch (allocation-free: __device__ globals)
__device__ float g_q [BATCH*NHEADS*SEQ*DHEAD];   // [B,H,L,dh] tf32-rounded (+q scaled)
__device__ float g_k [BATCH*NHEADS*SEQ*DHEAD];
__device__ float g_v [BATCH*NHEADS*SEQ*DHEAD];
__device__ float g_ao[MROWS*DMODEL];             // [B*L, D] tf32-rounded
__device__ float g_xr[MROWS*DMODEL];             // tf32-rounded x
__device__ float g_wr[4*DMODEL*DMODEL];          // tf32-rounded Wq,Wk,Wv,Wo

__device__ __forceinline__ float tf32f(float f) {
    uint32_t r;
    asm("cvt.rna.tf32.f32 %0, %1;" : "=r"(r) : "f"(f));
    return __uint_as_float(r);
}

#define LDSM4(r0,r1,r2,r3,addr) \
    asm volatile("ldmatrix.sync.aligned.m8n8.x4.shared.b16 {%0,%1,%2,%3}, [%4];" \
        : "=r"(r0),"=r"(r1),"=r"(r2),"=r"(r3) : "r"(addr))

#define MMA_TF32(c,a,b0,b1) \
    asm volatile("mma.sync.aligned.m16n8k8.row.col.f32.tf32.tf32.f32 " \
        "{%0,%1,%2,%3},{%4,%5,%6,%7},{%8,%9},{%0,%1,%2,%3};" \
        : "+f"(c[0]),"+f"(c[1]),"+f"(c[2]),"+f"(c[3]) \
        : "r"(a[0]),"r"(a[1]),"r"(a[2]),"r"(a[3]),"r"(b0),"r"(b1))

#define CP16(dst,src) \
    asm volatile("cp.async.cg.shared.global [%0], [%1], 16;" \
        :: "r"(dst), "l"(src) : "memory")
#define CPCOMMIT() asm volatile("cp.async.commit_group;" ::: "memory")
#define CPWAIT(n)  asm volatile("cp.async.wait_group %0;" :: "n"(n) : "memory")

// ---------------------------------------------------------------------------
// Pre-round passes: fp32 -> tf32-rounded fp32
// ---------------------------------------------------------------------------
__global__ void __launch_bounds__(256)
round_x_kernel(const float* __restrict__ src, float* __restrict__ dst, int n4)
{
    int i = blockIdx.x * 256 + threadIdx.x;
    if (i >= n4) return;
    float4 v = reinterpret_cast<const float4*>(src)[i];
    v.x = tf32f(v.x); v.y = tf32f(v.y); v.z = tf32f(v.z); v.w = tf32f(v.w);
    reinterpret_cast<float4*>(dst)[i] = v;
}

__global__ void __launch_bounds__(256)
round_w_kernel(const float* __restrict__ Wq, const float* __restrict__ Wk,
               const float* __restrict__ Wv, const float* __restrict__ Wo,
               float* __restrict__ dst)
{
    const int z = blockIdx.y;
    const float* src = (z == 0) ? Wq : (z == 1) ? Wk : (z == 2) ? Wv : Wo;
    int i = blockIdx.x * 256 + threadIdx.x;
    float4 v = reinterpret_cast<const float4*>(src)[i];
    v.x = tf32f(v.x); v.y = tf32f(v.y); v.z = tf32f(v.z); v.w = tf32f(v.w);
    reinterpret_cast<float4*>(dst + (size_t)z * DMODEL * DMODEL)[i] = v;
}

// ---------------------------------------------------------------------------
// tf32 GEMM: C = A @ W^T, operands pre-rounded. cp.async 3-stage pipeline.
// CTA 128x128x32, 256 threads (8 warps 2x4), warp tile 64x32.  (round 11)
// ---------------------------------------------------------------------------
#define GSTF  9216
#define GWOFF 4608
#define GEMM_SMEM_BYTES (3*GSTF*4)   // 110592

__device__ __forceinline__ void gemm_load_stage(
    const float* __restrict__ A, const float* __restrict__ W,
    int m0, int n0, int k0, uint32_t sb, int tid)
{
    #pragma unroll
    for (int it = 0; it < 4; it++) {
        int idx = tid + it * 256;
        int row = idx >> 3, cg = idx & 7;
        CP16(sb + (uint32_t)((row*36 + cg*4) * 4),
             (const void*)&A[(size_t)(m0 + row) * DMODEL + k0 + cg*4]);
        CP16(sb + (uint32_t)((GWOFF + row*36 + cg*4) * 4),
             (const void*)&W[(size_t)(n0 + row) * DMODEL + k0 + cg*4]);
    }
}

template<int PERMUTE, int ROUND>
__device__ __forceinline__ void gemm_core(
    const float* __restrict__ A, const float* __restrict__ W,
    float* __restrict__ C, float scale)
{
    extern __shared__ float sm[];
    const int tid  = threadIdx.x;
    const int lane = tid & 31;
    const int wid  = tid >> 5;
    const int m0 = blockIdx.y * 128;
    const int n0 = blockIdx.x * 128;
    const int wm = (wid & 1) * 64;
    const int wn = (wid >> 1) * 32;

    float c[4][4][4];
    #pragma unroll
    for (int i = 0; i < 4; i++)
        #pragma unroll
        for (int j = 0; j < 4; j++)
            #pragma unroll
            for (int r = 0; r < 4; r++) c[i][j][r] = 0.0f;

    uint32_t sb = (uint32_t)__cvta_generic_to_shared(sm);
    uint32_t a_addr[4], b_addr[2];
    #pragma unroll
    for (int i = 0; i < 4; i++)
        a_addr[i] = sb + ((wm + i*16 + (lane & 15)) * 36 + (lane >> 4) * 4) * 4;
    #pragma unroll
    for (int p = 0; p < 2; p++)
        b_addr[p] = sb + (GWOFF +
            (wn + p*16 + ((lane >> 4) & 1) * 8 + (lane & 7)) * 36
            + ((lane >> 3) & 1) * 4) * 4;

    const int NK = DMODEL / 32;

    gemm_load_stage(A, W, m0, n0, 0,  sb,            tid); CPCOMMIT();
    gemm_load_stage(A, W, m0, n0, 32, sb + GSTF*4,   tid); CPCOMMIT();
    gemm_load_stage(A, W, m0, n0, 64, sb + 2*GSTF*4, tid); CPCOMMIT();

    #pragma unroll 1
    for (int i = 0; i < NK; i++) {
        CPWAIT(2);
        __syncthreads();

        const uint32_t soff = (uint32_t)(i % 3) * (GSTF*4);
        #pragma unroll
        for (int s = 0; s < 4; s++) {
            uint32_t a[4][4], bb[2][4];
            #pragma unroll
            for (int ii = 0; ii < 4; ii++)
                LDSM4(a[ii][0], a[ii][1], a[ii][2], a[ii][3],
                      a_addr[ii] + soff + s*32);
            #pragma unroll
            for (int p = 0; p < 2; p++)
                LDSM4(bb[p][0], bb[p][1], bb[p][2], bb[p][3],
                      b_addr[p] + soff + s*32);
            #pragma unroll
            for (int ii = 0; ii < 4; ii++) {
                MMA_TF32(c[ii][0], a[ii], bb[0][0], bb[0][1]);
                MMA_TF32(c[ii][1], a[ii], bb[0][2], bb[0][3]);
                MMA_TF32(c[ii][2], a[ii], bb[1][0], bb[1][1]);
                MMA_TF32(c[ii][3], a[ii], bb[1][2], bb[1][3]);
            }
        }
        __syncthreads();
        if (i + 3 < NK)
            gemm_load_stage(A, W, m0, n0, (i+3)*32, sb + soff, tid);
        CPCOMMIT();
    }

    const int g  = lane >> 2;
    const int tq = lane & 3;
    #pragma unroll
    for (int i = 0; i < 4; i++) {
        #pragma unroll
        for (int j = 0; j < 4; j++) {
            int col = n0 + wn + j*8 + tq*2;
            #pragma unroll
            for (int t = 0; t < 2; t++) {
                int row = m0 + wm + i*16 + g + t*8;
                float v0 = c[i][j][2*t], v1 = c[i][j][2*t+1];
                if (ROUND) { v0 = tf32f(v0 * scale); v1 = tf32f(v1 * scale); }
                float2 v = make_float2(v0, v1);
                if (PERMUTE) {
                    int b = row >> 11, l = row & (SEQ - 1);
                    int h = col >> 6, d = col & 63;
                    *reinterpret_cast<float2*>(
                        &C[(((size_t)(b*NHEADS + h)) * SEQ + l) * DHEAD + d]) = v;
                } else {
                    *reinterpret_cast<float2*>(&C[(size_t)row * DMODEL + col]) = v;
                }
            }
        }
    }
}

__global__ void __launch_bounds__(256, 2)
gemm_qkv_kernel(const float* __restrict__ xr, const float* __restrict__ wr,
                float* __restrict__ q, float* __restrict__ k,
                float* __restrict__ v)
{
    const int z = blockIdx.z;
    const float* W = wr + (size_t)z * DMODEL * DMODEL;
    float* C = (z == 0) ? q : (z == 1) ? k : v;
    float scale = (z == 0) ? 0.125f : 1.0f;
    gemm_core<1, 1>(xr, W, C, scale);
}

__global__ void __launch_bounds__(256, 2)
gemm_o_kernel(const float* __restrict__ ao, const float* __restrict__ wr,
              float* __restrict__ out)
{
    gemm_core<0, 0>(ao, wr + (size_t)3 * DMODEL * DMODEL, out, 1.0f);
}

// ---------------------------------------------------------------------------
// Flash attention, tf32 mma (round 9 base). CTA = 128 q x (b,h), 128 threads,
// 4 warps, warp tile m32 x n64, BK=64. Single-buffered K/V, padded stride 68.
// NEW: V gather mapping r=(idx>>1)&63, cg=((idx>>6)&14)|(idx&1) — lane pairs
// read contiguous 32B (16 sectors/LDG vs 32); STS stays conflict-free.
// smem floats: Qs[128*68] | Ps[128*68] | Ks[64*68] | Vt[64*68] = 104448 B
// ---------------------------------------------------------------------------
#define AQS 0
#define APS 8704
#define AKS 17408
#define AVT 21760
#define ATTN_SMEM_BYTES (26112*4)   // 104448

__global__ void __launch_bounds__(128, 2)
attn_tf32(const float* __restrict__ gq, const float* __restrict__ gk,
          const float* __restrict__ gv, float* __restrict__ ao)
{
    extern __shared__ float sm[];
    float* Ps  = sm + APS;
    float* Vts = sm + AVT;

    const int tid  = threadIdx.x;
    const int lane = tid & 31;
    const int wid  = tid >> 5;                    // 0..3, owns 32 q rows
    const int bh = blockIdx.y;
    const int q0 = ((int)gridDim.x - 1 - (int)blockIdx.x) * 128;  // heavy first

    uint32_t smb  = (uint32_t)__cvta_generic_to_shared(sm);
    uint32_t qs_b = smb + AQS*4;
    uint32_t ps_b = smb + APS*4;
    uint32_t ks_b = smb + AKS*4;
    uint32_t vt_b = smb + AVT*4;

    const float4* qbase = reinterpret_cast<const float4*>(
        gq + ((size_t)bh * SEQ + q0) * DHEAD);
    const float* kko = gk + (size_t)bh * SEQ * DHEAD;
    const float4* vvo = reinterpret_cast<const float4*>(
        gv + (size_t)bh * SEQ * DHEAD);

    // Prologue: cp.async Q + K0, pair-coalesced transpose-gather V0
    #pragma unroll
    for (int it = 0; it < 16; it++) {
        int idx = tid + it * 128;
        int row = idx >> 4, cg = idx & 15;
        CP16(qs_b + (uint32_t)((row*68 + cg*4) * 4), (const void*)(qbase + idx));
    }
    #pragma unroll
    for (int it = 0; it < 8; it++) {
        int idx = tid + it * 128;
        int row = idx >> 4, cg = idx & 15;
        CP16(ks_b + (uint32_t)((row*68 + cg*4) * 4),
             (const void*)(kko + (size_t)row * DHEAD + cg*4));
    }
    CPCOMMIT();
    float4 ra[8];
    #pragma unroll
    for (int it = 0; it < 8; it++) {
        int idx = tid + it * 128;
        int r  = (idx >> 1) & 63;
        int cg = ((idx >> 6) & 14) | (idx & 1);
        ra[it] = vvo[r * 16 + cg];                // V[r][cg*4..+3]
    }

    // LDSM addresses
    uint32_t qa_addr[2], pa_addr[2];
    #pragma unroll
    for (int mi = 0; mi < 2; mi++) {
        uint32_t roff = ((wid*32 + mi*16 + (lane & 15)) * 68 + (lane >> 4) * 4) * 4;
        qa_addr[mi] = qs_b + roff;
        pa_addr[mi] = ps_b + roff;
    }
    uint32_t kb_addr[4], vb_addr[4];
    #pragma unroll
    for (int p = 0; p < 4; p++) {
        uint32_t roff = ((p*16 + ((lane >> 4) & 1) * 8 + (lane & 7)) * 68
                        + ((lane >> 3) & 1) * 4) * 4;
        kb_addr[p] = ks_b + roff;
        vb_addr[p] = vt_b + roff;
    }

    float m_i[2][2] = {{-1e30f, -1e30f}, {-1e30f, -1e30f}};
    float l_i[2][2] = {{0.0f, 0.0f}, {0.0f, 0.0f}};
    float o[2][8][4];
    #pragma unroll
    for (int mi = 0; mi < 2; mi++)
        #pragma unroll
        for (int j = 0; j < 8; j++)
            #pragma unroll
            for (int r = 0; r < 4; r++) o[mi][j][r] = 0.0f;

    const int g  = lane >> 2;
    const int tq = lane & 3;

    const int nkb = (q0 + 128) / 64;
    #pragma unroll 1
    for (int kb = 0; kb < nkb; kb++) {
        if (kb > 0) {
            __syncthreads();   // prev iter's K/V smem reads complete
            const float* knxt = kko + (size_t)kb * 64 * DHEAD;
            #pragma unroll
            for (int it = 0; it < 8; it++) {
                int idx = tid + it * 128;
                int row = idx >> 4, cg = idx & 15;
                CP16(ks_b + (uint32_t)((row*68 + cg*4) * 4),
                     (const void*)(knxt + (size_t)row * DHEAD + cg*4));
            }
            CPCOMMIT();
        }
        // Store prefetched V[kb] transposed into Vt (matches gather mapping;
        // even lanes banks 0-15, odd lanes +272%32=16 -> banks 16-31: clean)
        #pragma unroll
        for (int it = 0; it < 8; it++) {
            int idx = tid + it * 128;
            int r  = (idx >> 1) & 63;
            int cg = ((idx >> 6) & 14) | (idx & 1);
            Vts[(cg*4+0) * 68 + r] = ra[it].x;
            Vts[(cg*4+1) * 68 + r] = ra[it].y;
            Vts[(cg*4+2) * 68 + r] = ra[it].z;
            Vts[(cg*4+3) * 68 + r] = ra[it].w;
        }
        CPWAIT(0);
        __syncthreads();

        // S = Q @ K^T : warp m32 x n64 x k64
        float sf[2][8][4];
        #pragma unroll
        for (int mi = 0; mi < 2; mi++)
            #pragma unroll
            for (int j = 0; j < 8; j++)
                #pragma unroll
                for (int r = 0; r < 4; r++) sf[mi][j][r] = 0.0f;

        #pragma unroll
        for (int s = 0; s < 8; s++) {
            uint32_t a[2][4], bb[4][4];
            #pragma unroll
            for (int mi = 0; mi < 2; mi++)
                LDSM4(a[mi][0], a[mi][1], a[mi][2], a[mi][3], qa_addr[mi] + s*32);
            #pragma unroll
            for (int p = 0; p < 4; p++)
                LDSM4(bb[p][0], bb[p][1], bb[p][2], bb[p][3], kb_addr[p] + s*32);
            #pragma unroll
            for (int mi = 0; mi < 2; mi++)
                #pragma unroll
                for (int p = 0; p < 4; p++) {
                    MMA_TF32(sf[mi][2*p],   a[mi], bb[p][0], bb[p][1]);
                    MMA_TF32(sf[mi][2*p+1], a[mi], bb[p][2], bb[p][3]);
                }
        }

        // Causal mask (near diagonal only)
        const int k0 = kb * 64;
        if (k0 + 63 > q0 + wid*32) {
            #pragma unroll
            for (int mi = 0; mi < 2; mi++)
                #pragma unroll
                for (int t = 0; t < 2; t++) {
                    int qg = q0 + wid*32 + mi*16 + g + t*8;
                    #pragma unroll
                    for (int j = 0; j < 8; j++) {
                        int kg = k0 + j*8 + tq*2;
                        if (kg   > qg) sf[mi][j][2*t]   = -1e30f;
                        if (kg+1 > qg) sf[mi][j][2*t+1] = -1e30f;
                    }
                }
        }

        // Online softmax; write P (tf32) to warp-private Ps rows
        #pragma unroll
        for (int mi = 0; mi < 2; mi++)
            #pragma unroll
            for (int t = 0; t < 2; t++) {
                float mx = -1e30f;
                #pragma unroll
                for (int j = 0; j < 8; j++)
                    mx = fmaxf(mx, fmaxf(sf[mi][j][2*t], sf[mi][j][2*t+1]));
                mx = fmaxf(mx, __shfl_xor_sync(0xffffffffu, mx, 1));
                mx = fmaxf(mx, __shfl_xor_sync(0xffffffffu, mx, 2));
                float newm = fmaxf(m_i[mi][t], mx);
                float corr = __expf(m_i[mi][t] - newm);
                float rs = 0.0f;
                int prow = (wid*32 + mi*16 + g + t*8) * 68 + tq*2;
                #pragma unroll
                for (int j = 0; j < 8; j++) {
                    float p0 = __expf(sf[mi][j][2*t]   - newm);
                    float p1 = __expf(sf[mi][j][2*t+1] - newm);
                    rs += p0 + p1;
                    *reinterpret_cast<float2*>(&Ps[prow + j*8]) =
                        make_float2(tf32f(p0), tf32f(p1));
                }
                rs += __shfl_xor_sync(0xffffffffu, rs, 1);
                rs += __shfl_xor_sync(0xffffffffu, rs, 2);
                l_i[mi][t] = l_i[mi][t] * corr + rs;
                m_i[mi][t] = newm;
                #pragma unroll
                for (int j = 0; j < 8; j++) {
                    o[mi][j][2*t]   *= corr;
                    o[mi][j][2*t+1] *= corr;
                }
            }
        __syncwarp();

        // Prefetch V[kb+1] (pair-coalesced gather; latency hidden by PV mma)
        if (kb + 1 < nkb) {
            const float4* vnxt = vvo + (size_t)(kb+1) * 64 * DHEAD / 4;
            #pragma unroll
            for (int it = 0; it < 8; it++) {
                int idx = tid + it * 128;
                int r  = (idx >> 1) & 63;
                int cg = ((idx >> 6) & 14) | (idx & 1);
                ra[it] = vnxt[r * 16 + cg];
            }
        }

        // O += P @ V : warp m32(q) x n64(d) x k64(keys)
        #pragma unroll
        for (int s = 0; s < 8; s++) {
            uint32_t a[2][4], bb[4][4];
            #pragma unroll
            for (int mi = 0; mi < 2; mi++)
                LDSM4(a[mi][0], a[mi][1], a[mi][2], a[mi][3], pa_addr[mi] + s*32);
            #pragma unroll
            for (int p = 0; p < 4; p++)
                LDSM4(bb[p][0], bb[p][1], bb[p][2], bb[p][3], vb_addr[p] + s*32);
            #pragma unroll
            for (int mi = 0; mi < 2; mi++)
                #pragma unroll
                for (int p = 0; p < 4; p++) {
                    MMA_TF32(o[mi][2*p],   a[mi], bb[p][0], bb[p][1]);
                    MMA_TF32(o[mi][2*p+1], a[mi], bb[p][2], bb[p][3]);
                }
        }
    }

    // Normalize and write tf32-rounded to [B*L, D] (col = h*64 + d)
    const int b = bh >> 4;
    const int h = bh & 15;
    #pragma unroll
    for (int mi = 0; mi < 2; mi++)
        #pragma unroll
        for (int t = 0; t < 2; t++) {
            float inv = 1.0f / l_i[mi][t];
            int row = q0 + wid*32 + mi*16 + g + t*8;
            float* dst = ao + ((size_t)(b * SEQ + row)) * DMODEL + h * DHEAD + tq*2;
            #pragma unroll
            for (int j = 0; j < 8; j++)
                *reinterpret_cast<float2*>(dst + j*8) =
                    make_float2(tf32f(o[mi][j][2*t] * inv),
                                tf32f(o[mi][j][2*t+1] * inv));
        }
}

// ---------------------------------------------------------------------------
extern "C" void kernel_launch(void* const* d_in, const int* in_sizes, int n_in,
                              void* d_out, int out_size)
{
    const float* x  = (const float*)d_in[0];
    const float* Wq = (const float*)d_in[1];
    const float* Wk = (const float*)d_in[2];
    const float* Wv = (const float*)d_in[3];
    const float* Wo = (const float*)d_in[4];
    float* out = (float*)d_out;

    float *qp, *kp, *vp, *aop, *xrp, *wrp;
    cudaGetSymbolAddress((void**)&qp,  g_q);
    cudaGetSymbolAddress((void**)&kp,  g_k);
    cudaGetSymbolAddress((void**)&vp,  g_v);
    cudaGetSymbolAddress((void**)&aop, g_ao);
    cudaGetSymbolAddress((void**)&xrp, g_xr);
    cudaGetSymbolAddress((void**)&wrp, g_wr);

    cudaFuncSetAttribute(gemm_qkv_kernel,
        cudaFuncAttributeMaxDynamicSharedMemorySize, GEMM_SMEM_BYTES);
    cudaFuncSetAttribute(gemm_o_kernel,
        cudaFuncAttributeMaxDynamicSharedMemorySize, GEMM_SMEM_BYTES);
    cudaFuncSetAttribute(attn_tf32,
        cudaFuncAttributeMaxDynamicSharedMemorySize, ATTN_SMEM_BYTES);

    const int n4x = MROWS * DMODEL / 4;
    const int n4w = DMODEL * DMODEL / 4;
    round_x_kernel<<<n4x/256, 256>>>(x, xrp, n4x);
    dim3 wgrid(n4w/256, 4);
    round_w_kernel<<<wgrid, 256>>>(Wq, Wk, Wv, Wo, wrp);

    dim3 qkv_grid(DMODEL/128, MROWS/128, 3);   // (8, 64, 3)
    gemm_qkv_kernel<<<qkv_grid, 256, GEMM_SMEM_BYTES>>>(xrp, wrp, qp, kp, vp);

    dim3 attn_grid(SEQ/128, BATCH*NHEADS);     // (16, 64)
    attn_tf32<<<attn_grid, 128, ATTN_SMEM_BYTES>>>(qp, kp, vp, aop);

    dim3 o_grid(DMODEL/128, MROWS/128);        // (8, 64)
    gemm_o_kernel<<<o_grid, 256, GEMM_SMEM_BYTES>>>(aop, wrp, out);
}